// round 1
// baseline (speedup 1.0000x reference)
#include <cuda_runtime.h>
#include <cstdint>

// ---------------------------------------------------------------------------
// Problem constants
//   x:      [64, 1024, 512]  fp32
//   w_qkv:  [512, 1536]
//   w_proj: [512, 512]
//   b_proj: [512]
//   out:    [64, 1024, 512]
// Token n = h*64 + w on a 16x64 grid. Local window |dh|<=3, |dw|<=5.
// ---------------------------------------------------------------------------

#define NTOK   1024
#define BATCH  64
#define MTOT   (BATCH * NTOK)      // 65536
#define DIMSZ  512
#define QKVC   1536

// Scratch (device globals: allocation-free, graph-capturable)
static __device__ float g_qkv[(size_t)MTOT * QKVC];   // 402 MB
static __device__ float g_att[(size_t)MTOT * DIMSZ];  // 134 MB

// ---------------------------------------------------------------------------
// tf32 helpers
// ---------------------------------------------------------------------------
__device__ __forceinline__ uint32_t f2tf(float f) {
    uint32_t u;
    asm("cvt.rna.tf32.f32 %0, %1;" : "=r"(u) : "f"(f));
    return u;
}

__device__ __forceinline__ void mma8(float* c, const uint32_t* a, const uint32_t* b) {
    asm volatile(
        "mma.sync.aligned.m16n8k8.row.col.f32.tf32.tf32.f32 "
        "{%0,%1,%2,%3}, {%4,%5,%6,%7}, {%8,%9}, {%0,%1,%2,%3};"
        : "+f"(c[0]), "+f"(c[1]), "+f"(c[2]), "+f"(c[3])
        : "r"(a[0]), "r"(a[1]), "r"(a[2]), "r"(a[3]), "r"(b[0]), "r"(b[1]));
}

// ---------------------------------------------------------------------------
// Generic tf32 GEMM: C[M,N] = A[M,K] * B[K,N] (+bias), row-major fp32.
// Block tile 128x64, BK=32, 256 threads = 8 warps in a 4x2 grid,
// warp tile 32x32 (2 m-tiles x 4 n-tiles of m16n8k8).
// Requires M%128==0, N%64==0, K%32==0 (true for all uses here).
// ---------------------------------------------------------------------------
template <bool BIAS>
__global__ __launch_bounds__(256) void gemm_tf32_kernel(
    const float* __restrict__ A, const float* __restrict__ B,
    const float* __restrict__ bias, float* __restrict__ C,
    int N, int K)
{
    __shared__ float As[128][36];   // stride 36: (4*row+col)%32 -> conflict-free frags
    __shared__ float Bs[32][68];    // stride 68: same property

    const int tid  = threadIdx.x;
    const int lane = tid & 31;
    const int warp = tid >> 5;
    const int g    = lane >> 2;     // groupID (0..7)
    const int cc   = lane & 3;      // threadID_in_group (0..3)
    const int wr   = warp >> 1;     // 0..3
    const int wc   = warp & 1;      // 0..1
    const int bm   = blockIdx.y * 128;
    const int bn   = blockIdx.x * 64;

    float acc[2][4][4];
    #pragma unroll
    for (int mt = 0; mt < 2; mt++)
        #pragma unroll
        for (int nt = 0; nt < 4; nt++)
            #pragma unroll
            for (int r = 0; r < 4; r++) acc[mt][nt][r] = 0.f;

    for (int k0 = 0; k0 < K; k0 += 32) {
        // Load A tile 128x32 (4 float4 per thread), convert to tf32 bits
        #pragma unroll
        for (int i = 0; i < 4; i++) {
            int idx = tid + i * 256;
            int row = idx >> 3;
            int c4  = (idx & 7) * 4;
            float4 v = *reinterpret_cast<const float4*>(
                &A[(size_t)(bm + row) * K + k0 + c4]);
            As[row][c4 + 0] = __uint_as_float(f2tf(v.x));
            As[row][c4 + 1] = __uint_as_float(f2tf(v.y));
            As[row][c4 + 2] = __uint_as_float(f2tf(v.z));
            As[row][c4 + 3] = __uint_as_float(f2tf(v.w));
        }
        // Load B tile 32x64 (2 float4 per thread)
        #pragma unroll
        for (int i = 0; i < 2; i++) {
            int idx = tid + i * 256;
            int row = idx >> 4;
            int c4  = (idx & 15) * 4;
            float4 v = *reinterpret_cast<const float4*>(
                &B[(size_t)(k0 + row) * N + bn + c4]);
            Bs[row][c4 + 0] = __uint_as_float(f2tf(v.x));
            Bs[row][c4 + 1] = __uint_as_float(f2tf(v.y));
            Bs[row][c4 + 2] = __uint_as_float(f2tf(v.z));
            Bs[row][c4 + 3] = __uint_as_float(f2tf(v.w));
        }
        __syncthreads();

        #pragma unroll
        for (int kk = 0; kk < 4; kk++) {
            uint32_t af[2][4], bf[4][2];
            #pragma unroll
            for (int mt = 0; mt < 2; mt++) {
                int r0 = wr * 32 + mt * 16;
                af[mt][0] = __float_as_uint(As[r0 + g    ][kk * 8 + cc]);
                af[mt][1] = __float_as_uint(As[r0 + g + 8][kk * 8 + cc]);
                af[mt][2] = __float_as_uint(As[r0 + g    ][kk * 8 + cc + 4]);
                af[mt][3] = __float_as_uint(As[r0 + g + 8][kk * 8 + cc + 4]);
            }
            #pragma unroll
            for (int nt = 0; nt < 4; nt++) {
                int c0 = wc * 32 + nt * 8;
                bf[nt][0] = __float_as_uint(Bs[kk * 8 + cc    ][c0 + g]);
                bf[nt][1] = __float_as_uint(Bs[kk * 8 + cc + 4][c0 + g]);
            }
            #pragma unroll
            for (int mt = 0; mt < 2; mt++)
                #pragma unroll
                for (int nt = 0; nt < 4; nt++)
                    mma8(acc[mt][nt], af[mt], bf[nt]);
        }
        __syncthreads();
    }

    // Epilogue
    #pragma unroll
    for (int mt = 0; mt < 2; mt++) {
        #pragma unroll
        for (int nt = 0; nt < 4; nt++) {
            int row = bm + wr * 32 + mt * 16 + g;
            int col = bn + wc * 32 + nt * 8 + cc * 2;
            float b0 = 0.f, b1 = 0.f;
            if (BIAS) { b0 = bias[col]; b1 = bias[col + 1]; }
            float2 v0 = make_float2(acc[mt][nt][0] + b0, acc[mt][nt][1] + b1);
            float2 v1 = make_float2(acc[mt][nt][2] + b0, acc[mt][nt][3] + b1);
            *reinterpret_cast<float2*>(&C[(size_t)row * N + col])       = v0;
            *reinterpret_cast<float2*>(&C[(size_t)(row + 8) * N + col]) = v1;
        }
    }
}

// ---------------------------------------------------------------------------
// Local attention. One block per (hq, head, b): 64 queries (grid row hq,
// all w), key chunks = grid rows kh in [hq-3, hq+3] (64 keys each).
// 4 warps, each owns 16 query rows. Flash-style online softmax.
// Mask inside a chunk: |w_q - w_k| <= 5 (same band for every chunk).
// ---------------------------------------------------------------------------
__global__ __launch_bounds__(128) void attn_kernel(
    const float* __restrict__ qkv, float* __restrict__ attout)
{
    extern __shared__ float sm[];
    float* Qs = sm;                  // 64*68 floats; reused as P buffer later
    float* Ks = sm + 64 * 68;        // 64*68
    float* Vs = sm + 2 * 64 * 68;    // 64*68

    const int tid  = threadIdx.x;
    const int lane = tid & 31;
    const int warp = tid >> 5;
    const int g    = lane >> 2;
    const int cc   = lane & 3;
    const int hq   = blockIdx.x;
    const int head = blockIdx.y;
    const int b    = blockIdx.z;
    const int qrow = warp * 16;

    const float scale = 0.125f;   // 64^-0.5

    // ---- Load Q tile (scaled, tf32) ----
    {
        const float* qb = qkv + ((size_t)(b * NTOK + hq * 64)) * QKVC + head * 64;
        #pragma unroll
        for (int i = 0; i < 8; i++) {
            int idx = tid + i * 128;
            int row = idx >> 4;
            int c4  = (idx & 15) * 4;
            float4 v = *reinterpret_cast<const float4*>(&qb[(size_t)row * QKVC + c4]);
            Qs[row * 68 + c4 + 0] = __uint_as_float(f2tf(v.x * scale));
            Qs[row * 68 + c4 + 1] = __uint_as_float(f2tf(v.y * scale));
            Qs[row * 68 + c4 + 2] = __uint_as_float(f2tf(v.z * scale));
            Qs[row * 68 + c4 + 3] = __uint_as_float(f2tf(v.w * scale));
        }
    }
    __syncthreads();

    // Q fragments held in registers for all chunks (8 k-steps over d=64)
    uint32_t qa[8][4];
    #pragma unroll
    for (int kk = 0; kk < 8; kk++) {
        qa[kk][0] = __float_as_uint(Qs[(qrow + g    ) * 68 + kk * 8 + cc]);
        qa[kk][1] = __float_as_uint(Qs[(qrow + g + 8) * 68 + kk * 8 + cc]);
        qa[kk][2] = __float_as_uint(Qs[(qrow + g    ) * 68 + kk * 8 + cc + 4]);
        qa[kk][3] = __float_as_uint(Qs[(qrow + g + 8) * 68 + kk * 8 + cc + 4]);
    }
    __syncthreads();   // Qs now free -> reused as per-warp P buffer

    float o[8][4];
    #pragma unroll
    for (int nt = 0; nt < 8; nt++)
        #pragma unroll
        for (int r = 0; r < 4; r++) o[nt][r] = 0.f;
    float mrun[2] = {-1e30f, -1e30f};
    float lrun[2] = {0.f, 0.f};

    const int kh0 = (hq - 3 > 0)  ? hq - 3 : 0;
    const int kh1 = (hq + 3 < 15) ? hq + 3 : 15;

    for (int kh = kh0; kh <= kh1; kh++) {
        // ---- Load K,V chunk (64 keys x 64 dims each) ----
        const float* kb = qkv + ((size_t)(b * NTOK + kh * 64)) * QKVC + DIMSZ + head * 64;
        const float* vb = kb + DIMSZ;
        #pragma unroll
        for (int i = 0; i < 8; i++) {
            int idx = tid + i * 128;
            int row = idx >> 4;
            int c4  = (idx & 15) * 4;
            float4 kv = *reinterpret_cast<const float4*>(&kb[(size_t)row * QKVC + c4]);
            float4 vv = *reinterpret_cast<const float4*>(&vb[(size_t)row * QKVC + c4]);
            Ks[row * 68 + c4 + 0] = __uint_as_float(f2tf(kv.x));
            Ks[row * 68 + c4 + 1] = __uint_as_float(f2tf(kv.y));
            Ks[row * 68 + c4 + 2] = __uint_as_float(f2tf(kv.z));
            Ks[row * 68 + c4 + 3] = __uint_as_float(f2tf(kv.w));
            Vs[row * 68 + c4 + 0] = __uint_as_float(f2tf(vv.x));
            Vs[row * 68 + c4 + 1] = __uint_as_float(f2tf(vv.y));
            Vs[row * 68 + c4 + 2] = __uint_as_float(f2tf(vv.z));
            Vs[row * 68 + c4 + 3] = __uint_as_float(f2tf(vv.w));
        }
        __syncthreads();

        // ---- S = Q K^T  (16 q-rows x 64 keys per warp) ----
        float s[8][4];
        #pragma unroll
        for (int nt = 0; nt < 8; nt++)
            #pragma unroll
            for (int r = 0; r < 4; r++) s[nt][r] = 0.f;

        #pragma unroll
        for (int kk = 0; kk < 8; kk++) {
            #pragma unroll
            for (int nt = 0; nt < 8; nt++) {
                uint32_t bf[2];
                bf[0] = __float_as_uint(Ks[(nt * 8 + g) * 68 + kk * 8 + cc]);
                bf[1] = __float_as_uint(Ks[(nt * 8 + g) * 68 + kk * 8 + cc + 4]);
                mma8(s[nt], qa[kk], bf);
            }
        }

        // ---- Mask + online softmax ----
        float mloc[2] = {mrun[0], mrun[1]};
        #pragma unroll
        for (int nt = 0; nt < 8; nt++) {
            #pragma unroll
            for (int r = 0; r < 4; r++) {
                int qw = qrow + g + ((r >> 1) << 3);
                int kw = nt * 8 + cc * 2 + (r & 1);
                int d  = qw - kw;
                if (d > 5 || d < -5) s[nt][r] = -1e30f;
                mloc[r >> 1] = fmaxf(mloc[r >> 1], s[nt][r]);
            }
        }
        #pragma unroll
        for (int h = 0; h < 2; h++) {
            mloc[h] = fmaxf(mloc[h], __shfl_xor_sync(0xffffffffu, mloc[h], 1));
            mloc[h] = fmaxf(mloc[h], __shfl_xor_sync(0xffffffffu, mloc[h], 2));
        }
        float alpha[2];
        #pragma unroll
        for (int h = 0; h < 2; h++) {
            alpha[h] = __expf(mrun[h] - mloc[h]);
            mrun[h]  = mloc[h];
        }
        float rs[2] = {0.f, 0.f};
        #pragma unroll
        for (int nt = 0; nt < 8; nt++) {
            #pragma unroll
            for (int r = 0; r < 4; r++) {
                float p = __expf(s[nt][r] - mrun[r >> 1]);
                s[nt][r] = p;
                rs[r >> 1] += p;
            }
        }
        #pragma unroll
        for (int h = 0; h < 2; h++) {
            rs[h] += __shfl_xor_sync(0xffffffffu, rs[h], 1);
            rs[h] += __shfl_xor_sync(0xffffffffu, rs[h], 2);
            lrun[h] = lrun[h] * alpha[h] + rs[h];
        }
        #pragma unroll
        for (int nt = 0; nt < 8; nt++) {
            #pragma unroll
            for (int r = 0; r < 4; r++) o[nt][r] *= alpha[r >> 1];
        }

        // ---- Re-fragment P via warp-private smem slice (rows qrow..qrow+15) ----
        float* Ps = Qs;
        #pragma unroll
        for (int nt = 0; nt < 8; nt++) {
            float2 p0 = make_float2(__uint_as_float(f2tf(s[nt][0])),
                                    __uint_as_float(f2tf(s[nt][1])));
            float2 p1 = make_float2(__uint_as_float(f2tf(s[nt][2])),
                                    __uint_as_float(f2tf(s[nt][3])));
            *reinterpret_cast<float2*>(&Ps[(qrow + g    ) * 68 + nt * 8 + cc * 2]) = p0;
            *reinterpret_cast<float2*>(&Ps[(qrow + g + 8) * 68 + nt * 8 + cc * 2]) = p1;
        }
        __syncwarp();

        // ---- O += P V ----
        #pragma unroll
        for (int kk = 0; kk < 8; kk++) {
            uint32_t pa[4];
            pa[0] = __float_as_uint(Ps[(qrow + g    ) * 68 + kk * 8 + cc]);
            pa[1] = __float_as_uint(Ps[(qrow + g + 8) * 68 + kk * 8 + cc]);
            pa[2] = __float_as_uint(Ps[(qrow + g    ) * 68 + kk * 8 + cc + 4]);
            pa[3] = __float_as_uint(Ps[(qrow + g + 8) * 68 + kk * 8 + cc + 4]);
            #pragma unroll
            for (int nt = 0; nt < 8; nt++) {
                uint32_t vf[2];
                vf[0] = __float_as_uint(Vs[(kk * 8 + cc    ) * 68 + nt * 8 + g]);
                vf[1] = __float_as_uint(Vs[(kk * 8 + cc + 4) * 68 + nt * 8 + g]);
                mma8(o[nt], pa, vf);
            }
        }
        __syncthreads();   // protect Ks/Vs before next chunk's loads
    }

    // ---- Normalize + store ----
    float inv[2] = {1.f / lrun[0], 1.f / lrun[1]};
    float* ob = attout + ((size_t)(b * NTOK + hq * 64)) * DIMSZ + head * 64;
    #pragma unroll
    for (int nt = 0; nt < 8; nt++) {
        int col = nt * 8 + cc * 2;
        float2 v0 = make_float2(o[nt][0] * inv[0], o[nt][1] * inv[0]);
        float2 v1 = make_float2(o[nt][2] * inv[1], o[nt][3] * inv[1]);
        *reinterpret_cast<float2*>(&ob[(size_t)(qrow + g    ) * DIMSZ + col]) = v0;
        *reinterpret_cast<float2*>(&ob[(size_t)(qrow + g + 8) * DIMSZ + col]) = v1;
    }
}

// ---------------------------------------------------------------------------
// Launch
// ---------------------------------------------------------------------------
extern "C" void kernel_launch(void* const* d_in, const int* in_sizes, int n_in,
                              void* d_out, int out_size)
{
    (void)in_sizes; (void)n_in; (void)out_size;
    const float* x      = (const float*)d_in[0];
    const float* w_qkv  = (const float*)d_in[1];
    const float* w_proj = (const float*)d_in[2];
    const float* b_proj = (const float*)d_in[3];
    float* out = (float*)d_out;

    float *qkv_ptr = nullptr, *att_ptr = nullptr;
    cudaGetSymbolAddress((void**)&qkv_ptr, g_qkv);
    cudaGetSymbolAddress((void**)&att_ptr, g_att);

    const int attn_smem = 3 * 64 * 68 * (int)sizeof(float);  // 52224 B
    cudaFuncSetAttribute((const void*)attn_kernel,
                         cudaFuncAttributeMaxDynamicSharedMemorySize, attn_smem);

    // 1) QKV GEMM: [65536,512] x [512,1536] -> g_qkv
    gemm_tf32_kernel<false><<<dim3(QKVC / 64, MTOT / 128), 256>>>(
        x, w_qkv, nullptr, qkv_ptr, QKVC, DIMSZ);

    // 2) Local attention -> g_att  ([b, n, head*64+d])
    attn_kernel<<<dim3(16, 8, BATCH), 128, attn_smem>>>(qkv_ptr, att_ptr);

    // 3) Projection: [65536,512] x [512,512] + bias -> out
    gemm_tf32_kernel<true><<<dim3(DIMSZ / 64, MTOT / 128), 256>>>(
        att_ptr, w_proj, b_proj, out, DIMSZ, DIMSZ);
}

// round 2
// speedup vs baseline: 1.2228x; 1.2228x over previous
#include <cuda_runtime.h>
#include <cstdint>

// ---------------------------------------------------------------------------
//   x:[64,1024,512] fp32, w_qkv:[512,1536], w_proj:[512,512], b_proj:[512]
//   out:[64,1024,512]. Token n = h*64+w on 16x64 grid, window |dh|<=3,|dw|<=5.
// ---------------------------------------------------------------------------

#define NTOK   1024
#define BATCH  64
#define MTOT   (BATCH * NTOK)      // 65536
#define DIMSZ  512
#define QKVC   1536

static __device__ float g_qkv[(size_t)MTOT * QKVC];     // 402 MB
static __device__ float g_att[(size_t)MTOT * DIMSZ];    // 134 MB
static __device__ float g_wqkvT[QKVC * DIMSZ];          // transposed + tf32
static __device__ float g_wprojT[DIMSZ * DIMSZ];

// ---------------------------------------------------------------------------
// helpers
// ---------------------------------------------------------------------------
__device__ __forceinline__ uint32_t f2tf(float f) {
    uint32_t u;
    asm("cvt.rna.tf32.f32 %0, %1;" : "=r"(u) : "f"(f));
    return u;
}
__device__ __forceinline__ uint32_t cvt_bits(uint32_t x) {
    uint32_t u;
    asm("cvt.rna.tf32.f32 %0, %1;" : "=r"(u) : "f"(__uint_as_float(x)));
    return u;
}
__device__ __forceinline__ void mma8(float* c, const uint32_t* a,
                                     uint32_t b0, uint32_t b1) {
    asm volatile(
        "mma.sync.aligned.m16n8k8.row.col.f32.tf32.tf32.f32 "
        "{%0,%1,%2,%3}, {%4,%5,%6,%7}, {%8,%9}, {%0,%1,%2,%3};"
        : "+f"(c[0]), "+f"(c[1]), "+f"(c[2]), "+f"(c[3])
        : "r"(a[0]), "r"(a[1]), "r"(a[2]), "r"(a[3]), "r"(b0), "r"(b1));
}
__device__ __forceinline__ void ldsm4(uint32_t addr, uint32_t* r) {
    asm volatile("ldmatrix.sync.aligned.m8n8.x4.shared.b16 {%0,%1,%2,%3}, [%4];"
                 : "=r"(r[0]), "=r"(r[1]), "=r"(r[2]), "=r"(r[3]) : "r"(addr));
}
__device__ __forceinline__ void cpa16(uint32_t dst, const void* src) {
    asm volatile("cp.async.cg.shared.global [%0], [%1], 16;" :: "r"(dst), "l"(src));
}
__device__ __forceinline__ void cpa_commit() { asm volatile("cp.async.commit_group;"); }
template <int N>
__device__ __forceinline__ void cpa_wait() {
    asm volatile("cp.async.wait_group %0;" :: "n"(N));
}

// ---------------------------------------------------------------------------
// Pre-pass: WT[C][R] = tf32(W[R][C])
// ---------------------------------------------------------------------------
__global__ void transpose_cvt_kernel(const float* __restrict__ W,
                                     float* __restrict__ WT, int R, int C) {
    __shared__ float t[32][33];
    int c0 = blockIdx.x * 32, r0 = blockIdx.y * 32;
    int x = threadIdx.x, y = threadIdx.y;   // block (32, 8)
    #pragma unroll
    for (int i = 0; i < 32; i += 8)
        t[y + i][x] = __uint_as_float(f2tf(W[(size_t)(r0 + y + i) * C + c0 + x]));
    __syncthreads();
    #pragma unroll
    for (int i = 0; i < 32; i += 8)
        WT[(size_t)(c0 + y + i) * R + r0 + x] = t[x][y + i];
}

// ---------------------------------------------------------------------------
// GEMM: C[M,N] = A[M,K] (fp32, cvt'd in regs) * BT[N,K] (pre-tf32) (+bias)
// Block 128x64, BK=32, 256 thr = 8 warps (4m x 2n), warp tile 32x32.
// cp.async double-buffered; fragments via ldmatrix.
// ---------------------------------------------------------------------------
template <bool BIAS>
__global__ __launch_bounds__(256) void gemm_kernel(
    const float* __restrict__ A, const float* __restrict__ BT,
    const float* __restrict__ bias, float* __restrict__ C, int N, int K)
{
    extern __shared__ float sm[];
    const int ASZ = 128 * 36;        // floats per A stage
    const int BSZ = 64 * 36;

    const int tid  = threadIdx.x;
    const int lane = tid & 31;
    const int warp = tid >> 5;
    const int g    = lane >> 2;
    const int cc   = lane & 3;
    const int wr   = warp >> 1;      // 0..3
    const int wc   = warp & 1;       // 0..1
    const int bm   = blockIdx.y * 128;
    const int bn   = blockIdx.x * 64;

    const uint32_t smb = (uint32_t)__cvta_generic_to_shared(sm);
    const uint32_t bOff = 2u * ASZ * 4;

    // cp.async destinations (stage 0)
    const uint32_t aDst = smb + ((tid >> 3) * 36 + (tid & 7) * 4) * 4;
    const uint32_t bDst = smb + bOff + ((tid >> 3) * 36 + (tid & 7) * 4) * 4;
    const float* aSrc = A  + (size_t)(bm + (tid >> 3)) * K + (tid & 7) * 4;
    const float* bSrc = BT + (size_t)(bn + (tid >> 3)) * K + (tid & 7) * 4;

    // ldmatrix source addresses (stage 0): x4 = rows {rp, rp+8} x cols {0,+4}
    const int rowpat = (lane & 7) + ((lane >> 3) & 1) * 8;
    const int colpat = (lane >> 4) * 4;
    uint32_t aLd[2], bLd[2];
    #pragma unroll
    for (int mt = 0; mt < 2; mt++)
        aLd[mt] = smb + ((wr * 32 + mt * 16 + rowpat) * 36 + colpat) * 4;
    #pragma unroll
    for (int np = 0; np < 2; np++)
        bLd[np] = smb + bOff + ((wc * 32 + np * 16 + rowpat) * 36 + colpat) * 4;

    float acc[2][4][4];
    #pragma unroll
    for (int mt = 0; mt < 2; mt++)
        #pragma unroll
        for (int nt = 0; nt < 4; nt++)
            #pragma unroll
            for (int r = 0; r < 4; r++) acc[mt][nt][r] = 0.f;

    const int NIT = K >> 5;

    // prologue: stage 0
    #pragma unroll
    for (int i = 0; i < 4; i++) cpa16(aDst + i * 4608, aSrc + (size_t)i * 32 * K);
    #pragma unroll
    for (int i = 0; i < 2; i++) cpa16(bDst + i * 4608, bSrc + (size_t)i * 32 * K);
    cpa_commit();

    for (int it = 0; it < NIT; ++it) {
        const int cur = it & 1;
        if (it + 1 < NIT) {
            const int ko = (it + 1) * 32;
            const uint32_t sa = aDst + (cur ^ 1) * (ASZ * 4);
            const uint32_t sb = bDst + (cur ^ 1) * (BSZ * 4);
            #pragma unroll
            for (int i = 0; i < 4; i++) cpa16(sa + i * 4608, aSrc + (size_t)i * 32 * K + ko);
            #pragma unroll
            for (int i = 0; i < 2; i++) cpa16(sb + i * 4608, bSrc + (size_t)i * 32 * K + ko);
            cpa_commit();
            cpa_wait<1>();
        } else {
            cpa_wait<0>();
        }
        __syncthreads();

        const uint32_t sA = cur * (ASZ * 4);
        const uint32_t sB = cur * (BSZ * 4);
        #pragma unroll
        for (int kk = 0; kk < 4; kk++) {
            uint32_t af[2][4], bq[2][4];
            ldsm4(aLd[0] + sA + kk * 32, af[0]);
            ldsm4(aLd[1] + sA + kk * 32, af[1]);
            ldsm4(bLd[0] + sB + kk * 32, bq[0]);
            ldsm4(bLd[1] + sB + kk * 32, bq[1]);
            #pragma unroll
            for (int mt = 0; mt < 2; mt++)
                #pragma unroll
                for (int r = 0; r < 4; r++) af[mt][r] = cvt_bits(af[mt][r]);
            #pragma unroll
            for (int mt = 0; mt < 2; mt++) {
                mma8(acc[mt][0], af[mt], bq[0][0], bq[0][2]);
                mma8(acc[mt][1], af[mt], bq[0][1], bq[0][3]);
                mma8(acc[mt][2], af[mt], bq[1][0], bq[1][2]);
                mma8(acc[mt][3], af[mt], bq[1][1], bq[1][3]);
            }
        }
        __syncthreads();
    }

    // epilogue
    #pragma unroll
    for (int mt = 0; mt < 2; mt++) {
        #pragma unroll
        for (int nt = 0; nt < 4; nt++) {
            int row = bm + wr * 32 + mt * 16 + g;
            int col = bn + wc * 32 + nt * 8 + cc * 2;
            float b0 = 0.f, b1 = 0.f;
            if (BIAS) { b0 = bias[col]; b1 = bias[col + 1]; }
            float2 v0 = make_float2(acc[mt][nt][0] + b0, acc[mt][nt][1] + b1);
            float2 v1 = make_float2(acc[mt][nt][2] + b0, acc[mt][nt][3] + b1);
            *reinterpret_cast<float2*>(&C[(size_t)row * N + col])       = v0;
            *reinterpret_cast<float2*>(&C[(size_t)(row + 8) * N + col]) = v1;
        }
    }
}

// ---------------------------------------------------------------------------
// Local attention, one block per (hq, head, b). 4 warps x 16 q-rows.
// K/P fragments via ldmatrix; V via scalar LDS (trans pattern).
// ---------------------------------------------------------------------------
__global__ __launch_bounds__(128) void attn_kernel(
    const float* __restrict__ qkv, float* __restrict__ attout)
{
    extern __shared__ float sm[];
    float* Qs = sm;                  // 64*68; reused as P buffer
    float* Ks = sm + 64 * 68;
    float* Vs = sm + 2 * 64 * 68;

    const int tid  = threadIdx.x;
    const int lane = tid & 31;
    const int warp = tid >> 5;
    const int g    = lane >> 2;
    const int cc   = lane & 3;
    const int hq   = blockIdx.x;
    const int head = blockIdx.y;
    const int b    = blockIdx.z;
    const int qrow = warp * 16;

    const uint32_t smb = (uint32_t)__cvta_generic_to_shared(sm);
    const int rowpat = (lane & 7) + ((lane >> 3) & 1) * 8;
    const int colpat = (lane >> 4) * 4;
    const uint32_t ksB = smb + (64 * 68) * 4;
    uint32_t kAddr[4];
    #pragma unroll
    for (int np = 0; np < 4; np++)
        kAddr[np] = ksB + ((np * 16 + rowpat) * 68 + colpat) * 4;
    const uint32_t pAddr = smb + ((qrow + rowpat) * 68 + colpat) * 4;

    const float scale = 0.125f;

    // ---- Load Q (scaled, tf32) ----
    {
        const float* qb = qkv + ((size_t)(b * NTOK + hq * 64)) * QKVC + head * 64;
        #pragma unroll
        for (int i = 0; i < 8; i++) {
            int idx = tid + i * 128;
            int row = idx >> 4;
            int c4  = (idx & 15) * 4;
            float4 v = *reinterpret_cast<const float4*>(&qb[(size_t)row * QKVC + c4]);
            Qs[row * 68 + c4 + 0] = __uint_as_float(f2tf(v.x * scale));
            Qs[row * 68 + c4 + 1] = __uint_as_float(f2tf(v.y * scale));
            Qs[row * 68 + c4 + 2] = __uint_as_float(f2tf(v.z * scale));
            Qs[row * 68 + c4 + 3] = __uint_as_float(f2tf(v.w * scale));
        }
    }
    __syncthreads();

    uint32_t qa[8][4];
    #pragma unroll
    for (int kk = 0; kk < 8; kk++)
        ldsm4(pAddr + kk * 32, qa[kk]);   // Q frags (A-pattern on Qs rows qrow..)
    __syncthreads();                      // Qs free -> P buffer

    float o[8][4];
    #pragma unroll
    for (int nt = 0; nt < 8; nt++)
        #pragma unroll
        for (int r = 0; r < 4; r++) o[nt][r] = 0.f;
    float mrun[2] = {-1e30f, -1e30f};
    float lrun[2] = {0.f, 0.f};

    const int kh0 = (hq - 3 > 0)  ? hq - 3 : 0;
    const int kh1 = (hq + 3 < 15) ? hq + 3 : 15;

    for (int kh = kh0; kh <= kh1; kh++) {
        const float* kb = qkv + ((size_t)(b * NTOK + kh * 64)) * QKVC + DIMSZ + head * 64;
        const float* vb = kb + DIMSZ;
        #pragma unroll
        for (int i = 0; i < 8; i++) {
            int idx = tid + i * 128;
            int row = idx >> 4;
            int c4  = (idx & 15) * 4;
            float4 kv = *reinterpret_cast<const float4*>(&kb[(size_t)row * QKVC + c4]);
            float4 vv = *reinterpret_cast<const float4*>(&vb[(size_t)row * QKVC + c4]);
            Ks[row * 68 + c4 + 0] = __uint_as_float(f2tf(kv.x));
            Ks[row * 68 + c4 + 1] = __uint_as_float(f2tf(kv.y));
            Ks[row * 68 + c4 + 2] = __uint_as_float(f2tf(kv.z));
            Ks[row * 68 + c4 + 3] = __uint_as_float(f2tf(kv.w));
            Vs[row * 68 + c4 + 0] = __uint_as_float(f2tf(vv.x));
            Vs[row * 68 + c4 + 1] = __uint_as_float(f2tf(vv.y));
            Vs[row * 68 + c4 + 2] = __uint_as_float(f2tf(vv.z));
            Vs[row * 68 + c4 + 3] = __uint_as_float(f2tf(vv.w));
        }
        __syncthreads();

        // ---- S = Q K^T via ldmatrix ----
        float s[8][4];
        #pragma unroll
        for (int nt = 0; nt < 8; nt++)
            #pragma unroll
            for (int r = 0; r < 4; r++) s[nt][r] = 0.f;

        #pragma unroll
        for (int kk = 0; kk < 8; kk++) {
            #pragma unroll
            for (int np = 0; np < 4; np++) {
                uint32_t kq[4];
                ldsm4(kAddr[np] + kk * 32, kq);
                mma8(s[2 * np    ], qa[kk], kq[0], kq[2]);
                mma8(s[2 * np + 1], qa[kk], kq[1], kq[3]);
            }
        }

        // ---- Mask + online softmax ----
        float mloc[2] = {mrun[0], mrun[1]};
        #pragma unroll
        for (int nt = 0; nt < 8; nt++) {
            #pragma unroll
            for (int r = 0; r < 4; r++) {
                int qw = qrow + g + ((r >> 1) << 3);
                int kw = nt * 8 + cc * 2 + (r & 1);
                int d  = qw - kw;
                if (d > 5 || d < -5) s[nt][r] = -1e30f;
                mloc[r >> 1] = fmaxf(mloc[r >> 1], s[nt][r]);
            }
        }
        #pragma unroll
        for (int h = 0; h < 2; h++) {
            mloc[h] = fmaxf(mloc[h], __shfl_xor_sync(0xffffffffu, mloc[h], 1));
            mloc[h] = fmaxf(mloc[h], __shfl_xor_sync(0xffffffffu, mloc[h], 2));
        }
        float alpha[2];
        #pragma unroll
        for (int h = 0; h < 2; h++) {
            alpha[h] = __expf(mrun[h] - mloc[h]);
            mrun[h]  = mloc[h];
        }
        float rs[2] = {0.f, 0.f};
        #pragma unroll
        for (int nt = 0; nt < 8; nt++) {
            #pragma unroll
            for (int r = 0; r < 4; r++) {
                float p = __expf(s[nt][r] - mrun[r >> 1]);
                s[nt][r] = p;
                rs[r >> 1] += p;
            }
        }
        #pragma unroll
        for (int h = 0; h < 2; h++) {
            rs[h] += __shfl_xor_sync(0xffffffffu, rs[h], 1);
            rs[h] += __shfl_xor_sync(0xffffffffu, rs[h], 2);
            lrun[h] = lrun[h] * alpha[h] + rs[h];
        }
        #pragma unroll
        for (int nt = 0; nt < 8; nt++)
            #pragma unroll
            for (int r = 0; r < 4; r++) o[nt][r] *= alpha[r >> 1];

        // ---- P -> smem (tf32) -> A-frags via ldmatrix ----
        float* Ps = Qs;
        #pragma unroll
        for (int nt = 0; nt < 8; nt++) {
            float2 p0 = make_float2(__uint_as_float(f2tf(s[nt][0])),
                                    __uint_as_float(f2tf(s[nt][1])));
            float2 p1 = make_float2(__uint_as_float(f2tf(s[nt][2])),
                                    __uint_as_float(f2tf(s[nt][3])));
            *reinterpret_cast<float2*>(&Ps[(qrow + g    ) * 68 + nt * 8 + cc * 2]) = p0;
            *reinterpret_cast<float2*>(&Ps[(qrow + g + 8) * 68 + nt * 8 + cc * 2]) = p1;
        }
        __syncwarp();

        #pragma unroll
        for (int kk = 0; kk < 8; kk++) {
            uint32_t pa[4];
            ldsm4(pAddr + kk * 32, pa);
            #pragma unroll
            for (int nt = 0; nt < 8; nt++) {
                uint32_t vf0 = __float_as_uint(Vs[(kk * 8 + cc    ) * 68 + nt * 8 + g]);
                uint32_t vf1 = __float_as_uint(Vs[(kk * 8 + cc + 4) * 68 + nt * 8 + g]);
                mma8(o[nt], pa, vf0, vf1);
            }
        }
        __syncthreads();
    }

    float inv[2] = {1.f / lrun[0], 1.f / lrun[1]};
    float* ob = attout + ((size_t)(b * NTOK + hq * 64)) * DIMSZ + head * 64;
    #pragma unroll
    for (int nt = 0; nt < 8; nt++) {
        int col = nt * 8 + cc * 2;
        float2 v0 = make_float2(o[nt][0] * inv[0], o[nt][1] * inv[0]);
        float2 v1 = make_float2(o[nt][2] * inv[1], o[nt][3] * inv[1]);
        *reinterpret_cast<float2*>(&ob[(size_t)(qrow + g    ) * DIMSZ + col]) = v0;
        *reinterpret_cast<float2*>(&ob[(size_t)(qrow + g + 8) * DIMSZ + col]) = v1;
    }
}

// ---------------------------------------------------------------------------
extern "C" void kernel_launch(void* const* d_in, const int* in_sizes, int n_in,
                              void* d_out, int out_size)
{
    (void)in_sizes; (void)n_in; (void)out_size;
    const float* x      = (const float*)d_in[0];
    const float* w_qkv  = (const float*)d_in[1];
    const float* w_proj = (const float*)d_in[2];
    const float* b_proj = (const float*)d_in[3];
    float* out = (float*)d_out;

    float *qkv_ptr, *att_ptr, *wqkvT, *wprojT;
    cudaGetSymbolAddress((void**)&qkv_ptr, g_qkv);
    cudaGetSymbolAddress((void**)&att_ptr, g_att);
    cudaGetSymbolAddress((void**)&wqkvT, g_wqkvT);
    cudaGetSymbolAddress((void**)&wprojT, g_wprojT);

    const int gemm_smem = (2 * 128 * 36 + 2 * 64 * 36) * (int)sizeof(float); // 55296
    const int attn_smem = 3 * 64 * 68 * (int)sizeof(float);                  // 52224
    cudaFuncSetAttribute((const void*)gemm_kernel<false>,
                         cudaFuncAttributeMaxDynamicSharedMemorySize, gemm_smem);
    cudaFuncSetAttribute((const void*)gemm_kernel<true>,
                         cudaFuncAttributeMaxDynamicSharedMemorySize, gemm_smem);
    cudaFuncSetAttribute((const void*)attn_kernel,
                         cudaFuncAttributeMaxDynamicSharedMemorySize, attn_smem);

    // 0) Pre-transpose + tf32-round weights
    transpose_cvt_kernel<<<dim3(QKVC / 32, DIMSZ / 32), dim3(32, 8)>>>(
        w_qkv, wqkvT, DIMSZ, QKVC);
    transpose_cvt_kernel<<<dim3(DIMSZ / 32, DIMSZ / 32), dim3(32, 8)>>>(
        w_proj, wprojT, DIMSZ, DIMSZ);

    // 1) QKV GEMM
    gemm_kernel<false><<<dim3(QKVC / 64, MTOT / 128), 256, gemm_smem>>>(
        x, wqkvT, nullptr, qkv_ptr, QKVC, DIMSZ);

    // 2) Local attention
    attn_kernel<<<dim3(16, 8, BATCH), 128, attn_smem>>>(qkv_ptr, att_ptr);

    // 3) Projection
    gemm_kernel<true><<<dim3(DIMSZ / 64, MTOT / 128), 256, gemm_smem>>>(
        att_ptr, wprojT, b_proj, out, DIMSZ, DIMSZ);
}

// round 3
// speedup vs baseline: 1.4088x; 1.1521x over previous
#include <cuda_runtime.h>
#include <cstdint>

// ---------------------------------------------------------------------------
//   x:[64,1024,512] fp32, w_qkv:[512,1536], w_proj:[512,512], b_proj:[512]
//   out:[64,1024,512]. Token n = h*64+w on 16x64 grid, window |dh|<=3,|dw|<=5.
// ---------------------------------------------------------------------------

#define NTOK   1024
#define BATCH  64
#define MTOT   (BATCH * NTOK)      // 65536
#define DIMSZ  512
#define QKVC   1536

static __device__ float g_qkv[(size_t)MTOT * QKVC];     // 402 MB
static __device__ float g_att[(size_t)MTOT * DIMSZ];    // 134 MB
static __device__ float g_wqkvT[QKVC * DIMSZ];          // transposed + tf32
static __device__ float g_wprojT[DIMSZ * DIMSZ];

// ---------------------------------------------------------------------------
__device__ __forceinline__ uint32_t f2tf(float f) {
    uint32_t u;
    asm("cvt.rna.tf32.f32 %0, %1;" : "=r"(u) : "f"(f));
    return u;
}
__device__ __forceinline__ uint32_t cvt_bits(uint32_t x) {
    uint32_t u;
    asm("cvt.rna.tf32.f32 %0, %1;" : "=r"(u) : "f"(__uint_as_float(x)));
    return u;
}
__device__ __forceinline__ void mma8(float* c, const uint32_t* a,
                                     uint32_t b0, uint32_t b1) {
    asm volatile(
        "mma.sync.aligned.m16n8k8.row.col.f32.tf32.tf32.f32 "
        "{%0,%1,%2,%3}, {%4,%5,%6,%7}, {%8,%9}, {%0,%1,%2,%3};"
        : "+f"(c[0]), "+f"(c[1]), "+f"(c[2]), "+f"(c[3])
        : "r"(a[0]), "r"(a[1]), "r"(a[2]), "r"(a[3]), "r"(b0), "r"(b1));
}
__device__ __forceinline__ void ldsm4(uint32_t addr, uint32_t* r) {
    asm volatile("ldmatrix.sync.aligned.m8n8.x4.shared.b16 {%0,%1,%2,%3}, [%4];"
                 : "=r"(r[0]), "=r"(r[1]), "=r"(r[2]), "=r"(r[3]) : "r"(addr));
}
__device__ __forceinline__ void cpa16(uint32_t dst, const void* src) {
    asm volatile("cp.async.cg.shared.global [%0], [%1], 16;" :: "r"(dst), "l"(src));
}
__device__ __forceinline__ void cpa_commit() { asm volatile("cp.async.commit_group;"); }
template <int N>
__device__ __forceinline__ void cpa_wait() {
    asm volatile("cp.async.wait_group %0;" :: "n"(N));
}

// ---------------------------------------------------------------------------
// Pre-pass: WT[C][R] = tf32(W[R][C])
// ---------------------------------------------------------------------------
__global__ void transpose_cvt_kernel(const float* __restrict__ W,
                                     float* __restrict__ WT, int R, int C) {
    __shared__ float t[32][33];
    int c0 = blockIdx.x * 32, r0 = blockIdx.y * 32;
    int x = threadIdx.x, y = threadIdx.y;   // block (32, 8)
    #pragma unroll
    for (int i = 0; i < 32; i += 8)
        t[y + i][x] = __uint_as_float(f2tf(W[(size_t)(r0 + y + i) * C + c0 + x]));
    __syncthreads();
    #pragma unroll
    for (int i = 0; i < 32; i += 8)
        WT[(size_t)(c0 + y + i) * R + r0 + x] = t[x][y + i];
}

// ---------------------------------------------------------------------------
// GEMM: C[M,N] = A[M,K] * BT[N,K] (+bias). Block 128x128, BK=32, 256 thr,
// 8 warps (2m x 4n), warp tile 64x32. cp.async double-buffered + ldmatrix.
// DOCVT: convert A fragments to tf32 in regs (A fp32); else A already tf32.
// ---------------------------------------------------------------------------
template <bool BIAS, bool DOCVT>
__global__ __launch_bounds__(256) void gemm_kernel(
    const float* __restrict__ A, const float* __restrict__ BT,
    const float* __restrict__ bias, float* __restrict__ C, int N, int K)
{
    extern __shared__ float sm[];
    const int TSZ = 128 * 36;       // floats per stage (A and B identical)

    const int tid  = threadIdx.x;
    const int lane = tid & 31;
    const int warp = tid >> 5;
    const int g    = lane >> 2;
    const int cc   = lane & 3;
    const int wr   = warp >> 2;     // 0..1
    const int wc   = warp & 3;      // 0..3
    const int bm   = blockIdx.y * 128;
    const int bn   = blockIdx.x * 128;

    const uint32_t smb  = (uint32_t)__cvta_generic_to_shared(sm);
    const uint32_t bOff = 2u * TSZ * 4;

    const int ldrow = tid >> 3;
    const int ldcol = (tid & 7) * 4;
    const uint32_t aDst = smb + (ldrow * 36 + ldcol) * 4;
    const uint32_t bDst = smb + bOff + (ldrow * 36 + ldcol) * 4;
    const float* aSrc = A  + (size_t)(bm + ldrow) * K + ldcol;
    const float* bSrc = BT + (size_t)(bn + ldrow) * K + ldcol;

    const int rowpat = (lane & 7) + ((lane >> 3) & 1) * 8;
    const int colpat = (lane >> 4) * 4;
    uint32_t aLd[4], bLd[2];
    #pragma unroll
    for (int mt = 0; mt < 4; mt++)
        aLd[mt] = smb + ((wr * 64 + mt * 16 + rowpat) * 36 + colpat) * 4;
    #pragma unroll
    for (int np = 0; np < 2; np++)
        bLd[np] = smb + bOff + ((wc * 32 + np * 16 + rowpat) * 36 + colpat) * 4;

    float acc[4][4][4];
    #pragma unroll
    for (int mt = 0; mt < 4; mt++)
        #pragma unroll
        for (int nt = 0; nt < 4; nt++)
            #pragma unroll
            for (int r = 0; r < 4; r++) acc[mt][nt][r] = 0.f;

    const int NIT = K >> 5;

    #pragma unroll
    for (int i = 0; i < 4; i++) cpa16(aDst + i * 4608, aSrc + (size_t)i * 32 * K);
    #pragma unroll
    for (int i = 0; i < 4; i++) cpa16(bDst + i * 4608, bSrc + (size_t)i * 32 * K);
    cpa_commit();

    for (int it = 0; it < NIT; ++it) {
        const int cur = it & 1;
        if (it + 1 < NIT) {
            const int ko = (it + 1) * 32;
            const uint32_t sa = aDst + (cur ^ 1) * (TSZ * 4);
            const uint32_t sb = bDst + (cur ^ 1) * (TSZ * 4);
            #pragma unroll
            for (int i = 0; i < 4; i++) cpa16(sa + i * 4608, aSrc + (size_t)i * 32 * K + ko);
            #pragma unroll
            for (int i = 0; i < 4; i++) cpa16(sb + i * 4608, bSrc + (size_t)i * 32 * K + ko);
            cpa_commit();
            cpa_wait<1>();
        } else {
            cpa_wait<0>();
        }
        __syncthreads();

        const uint32_t st = cur * (TSZ * 4);
        #pragma unroll
        for (int kk = 0; kk < 4; kk++) {
            uint32_t af[4][4], bq[2][4];
            #pragma unroll
            for (int mt = 0; mt < 4; mt++) ldsm4(aLd[mt] + st + kk * 32, af[mt]);
            ldsm4(bLd[0] + st + kk * 32, bq[0]);
            ldsm4(bLd[1] + st + kk * 32, bq[1]);
            if (DOCVT) {
                #pragma unroll
                for (int mt = 0; mt < 4; mt++)
                    #pragma unroll
                    for (int r = 0; r < 4; r++) af[mt][r] = cvt_bits(af[mt][r]);
            }
            #pragma unroll
            for (int mt = 0; mt < 4; mt++) {
                mma8(acc[mt][0], af[mt], bq[0][0], bq[0][2]);
                mma8(acc[mt][1], af[mt], bq[0][1], bq[0][3]);
                mma8(acc[mt][2], af[mt], bq[1][0], bq[1][2]);
                mma8(acc[mt][3], af[mt], bq[1][1], bq[1][3]);
            }
        }
        __syncthreads();
    }

    #pragma unroll
    for (int mt = 0; mt < 4; mt++) {
        #pragma unroll
        for (int nt = 0; nt < 4; nt++) {
            int row = bm + wr * 64 + mt * 16 + g;
            int col = bn + wc * 32 + nt * 8 + cc * 2;
            float b0 = 0.f, b1 = 0.f;
            if (BIAS) { b0 = bias[col]; b1 = bias[col + 1]; }
            float2 v0 = make_float2(acc[mt][nt][0] + b0, acc[mt][nt][1] + b1);
            float2 v1 = make_float2(acc[mt][nt][2] + b0, acc[mt][nt][3] + b1);
            *reinterpret_cast<float2*>(&C[(size_t)row * N + col])       = v0;
            *reinterpret_cast<float2*>(&C[(size_t)(row + 8) * N + col]) = v1;
        }
    }
}

// ---------------------------------------------------------------------------
// Local attention, one block per (hq, head, b). 4 warps x 16 q-cols.
// Band-sparse: warp's 16 queries (w = qrow..qrow+15) only see 32-key window
// starting at k0 = clamp(qrow-8, 0, 32). S is 16x32, PV contracts 32 keys.
// Output stored tf32-rounded (GEMM2 skips cvt).
// ---------------------------------------------------------------------------
__global__ __launch_bounds__(128) void attn_kernel(
    const float* __restrict__ qkv, float* __restrict__ attout)
{
    extern __shared__ float sm[];
    float* Qs = sm;                  // 64*68; reused as P buffer
    float* Ks = sm + 64 * 68;
    float* Vs = sm + 2 * 64 * 68;

    const int tid  = threadIdx.x;
    const int lane = tid & 31;
    const int warp = tid >> 5;
    const int g    = lane >> 2;
    const int cc   = lane & 3;
    const int hq   = blockIdx.x;
    const int head = blockIdx.y;
    const int b    = blockIdx.z;
    const int qrow = warp * 16;
    const int k0   = (qrow - 8 < 0) ? 0 : (qrow - 8 > 32 ? 32 : qrow - 8);

    const uint32_t smb = (uint32_t)__cvta_generic_to_shared(sm);
    const int rowpat = (lane & 7) + ((lane >> 3) & 1) * 8;
    const int colpat = (lane >> 4) * 4;
    const uint32_t ksB = smb + (64 * 68) * 4;
    uint32_t kAddr[2];
    #pragma unroll
    for (int np = 0; np < 2; np++)
        kAddr[np] = ksB + ((k0 + np * 16 + rowpat) * 68 + colpat) * 4;
    const uint32_t pAddr = smb + ((qrow + rowpat) * 68 + colpat) * 4;

    const float scale = 0.125f;

    // ---- Load Q (scaled, tf32) ----
    {
        const float* qb = qkv + ((size_t)(b * NTOK + hq * 64)) * QKVC + head * 64;
        #pragma unroll
        for (int i = 0; i < 8; i++) {
            int idx = tid + i * 128;
            int row = idx >> 4;
            int c4  = (idx & 15) * 4;
            float4 v = *reinterpret_cast<const float4*>(&qb[(size_t)row * QKVC + c4]);
            Qs[row * 68 + c4 + 0] = __uint_as_float(f2tf(v.x * scale));
            Qs[row * 68 + c4 + 1] = __uint_as_float(f2tf(v.y * scale));
            Qs[row * 68 + c4 + 2] = __uint_as_float(f2tf(v.z * scale));
            Qs[row * 68 + c4 + 3] = __uint_as_float(f2tf(v.w * scale));
        }
    }
    __syncthreads();

    uint32_t qa[8][4];
    #pragma unroll
    for (int kk = 0; kk < 8; kk++)
        ldsm4(pAddr + kk * 32, qa[kk]);
    __syncthreads();                 // Qs free -> P buffer

    float o[8][4];
    #pragma unroll
    for (int nt = 0; nt < 8; nt++)
        #pragma unroll
        for (int r = 0; r < 4; r++) o[nt][r] = 0.f;
    float mrun[2] = {-1e30f, -1e30f};
    float lrun[2] = {0.f, 0.f};

    const int kh0 = (hq - 3 > 0)  ? hq - 3 : 0;
    const int kh1 = (hq + 3 < 15) ? hq + 3 : 15;

    for (int kh = kh0; kh <= kh1; kh++) {
        const float* kb = qkv + ((size_t)(b * NTOK + kh * 64)) * QKVC + DIMSZ + head * 64;
        const float* vb = kb + DIMSZ;
        #pragma unroll
        for (int i = 0; i < 8; i++) {
            int idx = tid + i * 128;
            int row = idx >> 4;
            int c4  = (idx & 15) * 4;
            float4 kv = *reinterpret_cast<const float4*>(&kb[(size_t)row * QKVC + c4]);
            float4 vv = *reinterpret_cast<const float4*>(&vb[(size_t)row * QKVC + c4]);
            Ks[row * 68 + c4 + 0] = __uint_as_float(f2tf(kv.x));
            Ks[row * 68 + c4 + 1] = __uint_as_float(f2tf(kv.y));
            Ks[row * 68 + c4 + 2] = __uint_as_float(f2tf(kv.z));
            Ks[row * 68 + c4 + 3] = __uint_as_float(f2tf(kv.w));
            Vs[row * 68 + c4 + 0] = __uint_as_float(f2tf(vv.x));
            Vs[row * 68 + c4 + 1] = __uint_as_float(f2tf(vv.y));
            Vs[row * 68 + c4 + 2] = __uint_as_float(f2tf(vv.z));
            Vs[row * 68 + c4 + 3] = __uint_as_float(f2tf(vv.w));
        }
        __syncthreads();

        // ---- S = Q K^T over this warp's 32-key window ----
        float s[4][4];
        #pragma unroll
        for (int nt = 0; nt < 4; nt++)
            #pragma unroll
            for (int r = 0; r < 4; r++) s[nt][r] = 0.f;

        #pragma unroll
        for (int kk = 0; kk < 8; kk++) {
            #pragma unroll
            for (int np = 0; np < 2; np++) {
                uint32_t kq[4];
                ldsm4(kAddr[np] + kk * 32, kq);
                mma8(s[2 * np    ], qa[kk], kq[0], kq[2]);
                mma8(s[2 * np + 1], qa[kk], kq[1], kq[3]);
            }
        }

        // ---- Mask + online softmax ----
        float mloc[2] = {mrun[0], mrun[1]};
        #pragma unroll
        for (int nt = 0; nt < 4; nt++) {
            #pragma unroll
            for (int r = 0; r < 4; r++) {
                int qw = qrow + g + ((r >> 1) << 3);
                int kw = k0 + nt * 8 + cc * 2 + (r & 1);
                int d  = qw - kw;
                if (d > 5 || d < -5) s[nt][r] = -1e30f;
                mloc[r >> 1] = fmaxf(mloc[r >> 1], s[nt][r]);
            }
        }
        #pragma unroll
        for (int h = 0; h < 2; h++) {
            mloc[h] = fmaxf(mloc[h], __shfl_xor_sync(0xffffffffu, mloc[h], 1));
            mloc[h] = fmaxf(mloc[h], __shfl_xor_sync(0xffffffffu, mloc[h], 2));
        }
        float alpha[2];
        #pragma unroll
        for (int h = 0; h < 2; h++) {
            alpha[h] = __expf(mrun[h] - mloc[h]);
            mrun[h]  = mloc[h];
        }
        float rs[2] = {0.f, 0.f};
        #pragma unroll
        for (int nt = 0; nt < 4; nt++) {
            #pragma unroll
            for (int r = 0; r < 4; r++) {
                float p = __expf(s[nt][r] - mrun[r >> 1]);
                s[nt][r] = p;
                rs[r >> 1] += p;
            }
        }
        #pragma unroll
        for (int h = 0; h < 2; h++) {
            rs[h] += __shfl_xor_sync(0xffffffffu, rs[h], 1);
            rs[h] += __shfl_xor_sync(0xffffffffu, rs[h], 2);
            lrun[h] = lrun[h] * alpha[h] + rs[h];
        }
        #pragma unroll
        for (int nt = 0; nt < 8; nt++)
            #pragma unroll
            for (int r = 0; r < 4; r++) o[nt][r] *= alpha[r >> 1];

        // ---- P (16x32, window-relative cols) -> smem -> A-frags ----
        float* Ps = Qs;
        #pragma unroll
        for (int nt = 0; nt < 4; nt++) {
            float2 p0 = make_float2(__uint_as_float(f2tf(s[nt][0])),
                                    __uint_as_float(f2tf(s[nt][1])));
            float2 p1 = make_float2(__uint_as_float(f2tf(s[nt][2])),
                                    __uint_as_float(f2tf(s[nt][3])));
            *reinterpret_cast<float2*>(&Ps[(qrow + g    ) * 68 + nt * 8 + cc * 2]) = p0;
            *reinterpret_cast<float2*>(&Ps[(qrow + g + 8) * 68 + nt * 8 + cc * 2]) = p1;
        }
        __syncwarp();

        // ---- O += P V  (32-key contraction) ----
        #pragma unroll
        for (int kk = 0; kk < 4; kk++) {
            uint32_t pa[4];
            ldsm4(pAddr + kk * 32, pa);
            const int krow = k0 + kk * 8;
            #pragma unroll
            for (int nt = 0; nt < 8; nt++) {
                uint32_t vf0 = __float_as_uint(Vs[(krow + cc    ) * 68 + nt * 8 + g]);
                uint32_t vf1 = __float_as_uint(Vs[(krow + cc + 4) * 68 + nt * 8 + g]);
                mma8(o[nt], pa, vf0, vf1);
            }
        }
        __syncthreads();
    }

    float inv[2] = {1.f / lrun[0], 1.f / lrun[1]};
    float* ob = attout + ((size_t)(b * NTOK + hq * 64)) * DIMSZ + head * 64;
    #pragma unroll
    for (int nt = 0; nt < 8; nt++) {
        int col = nt * 8 + cc * 2;
        float2 v0 = make_float2(__uint_as_float(f2tf(o[nt][0] * inv[0])),
                                __uint_as_float(f2tf(o[nt][1] * inv[0])));
        float2 v1 = make_float2(__uint_as_float(f2tf(o[nt][2] * inv[1])),
                                __uint_as_float(f2tf(o[nt][3] * inv[1])));
        *reinterpret_cast<float2*>(&ob[(size_t)(qrow + g    ) * DIMSZ + col]) = v0;
        *reinterpret_cast<float2*>(&ob[(size_t)(qrow + g + 8) * DIMSZ + col]) = v1;
    }
}

// ---------------------------------------------------------------------------
extern "C" void kernel_launch(void* const* d_in, const int* in_sizes, int n_in,
                              void* d_out, int out_size)
{
    (void)in_sizes; (void)n_in; (void)out_size;
    const float* x      = (const float*)d_in[0];
    const float* w_qkv  = (const float*)d_in[1];
    const float* w_proj = (const float*)d_in[2];
    const float* b_proj = (const float*)d_in[3];
    float* out = (float*)d_out;

    float *qkv_ptr, *att_ptr, *wqkvT, *wprojT;
    cudaGetSymbolAddress((void**)&qkv_ptr, g_qkv);
    cudaGetSymbolAddress((void**)&att_ptr, g_att);
    cudaGetSymbolAddress((void**)&wqkvT, g_wqkvT);
    cudaGetSymbolAddress((void**)&wprojT, g_wprojT);

    const int gemm_smem = 4 * 128 * 36 * (int)sizeof(float);   // 73728
    const int attn_smem = 3 * 64 * 68 * (int)sizeof(float);    // 52224
    cudaFuncSetAttribute((const void*)gemm_kernel<false, true>,
                         cudaFuncAttributeMaxDynamicSharedMemorySize, gemm_smem);
    cudaFuncSetAttribute((const void*)gemm_kernel<true, false>,
                         cudaFuncAttributeMaxDynamicSharedMemorySize, gemm_smem);
    cudaFuncSetAttribute((const void*)attn_kernel,
                         cudaFuncAttributeMaxDynamicSharedMemorySize, attn_smem);

    // 0) Pre-transpose + tf32-round weights
    transpose_cvt_kernel<<<dim3(QKVC / 32, DIMSZ / 32), dim3(32, 8)>>>(
        w_qkv, wqkvT, DIMSZ, QKVC);
    transpose_cvt_kernel<<<dim3(DIMSZ / 32, DIMSZ / 32), dim3(32, 8)>>>(
        w_proj, wprojT, DIMSZ, DIMSZ);

    // 1) QKV GEMM
    gemm_kernel<false, true><<<dim3(QKVC / 128, MTOT / 128), 256, gemm_smem>>>(
        x, wqkvT, nullptr, qkv_ptr, QKVC, DIMSZ);

    // 2) Local attention (output tf32-rounded)
    attn_kernel<<<dim3(16, 8, BATCH), 128, attn_smem>>>(qkv_ptr, att_ptr);

    // 3) Projection (A already tf32)
    gemm_kernel<true, false><<<dim3(DIMSZ / 128, MTOT / 128), 256, gemm_smem>>>(
        att_ptr, wprojT, b_proj, out, DIMSZ, DIMSZ);
}

// round 4
// speedup vs baseline: 1.5216x; 1.0801x over previous
#include <cuda_runtime.h>
#include <cstdint>

// ---------------------------------------------------------------------------
//   x:[64,1024,512] fp32, w_qkv:[512,1536], w_proj:[512,512], b_proj:[512]
//   out:[64,1024,512]. Token n = h*64+w on 16x64 grid, window |dh|<=3,|dw|<=5.
// ---------------------------------------------------------------------------

#define NTOK   1024
#define BATCH  64
#define MTOT   (BATCH * NTOK)      // 65536
#define DIMSZ  512
#define QKVC   1536

static __device__ float g_qkv[(size_t)MTOT * QKVC];     // 402 MB (tf32 values)
static __device__ float g_att[(size_t)MTOT * DIMSZ];    // 134 MB (tf32 values)
static __device__ float g_xtf[(size_t)MTOT * DIMSZ];    // 134 MB (tf32 of x)
static __device__ float g_wqkvT[QKVC * DIMSZ];          // transposed + tf32
static __device__ float g_wprojT[DIMSZ * DIMSZ];

// ---------------------------------------------------------------------------
__device__ __forceinline__ uint32_t f2tf(float f) {
    uint32_t u;
    asm("cvt.rna.tf32.f32 %0, %1;" : "=r"(u) : "f"(f));
    return u;
}
__device__ __forceinline__ void mma8(float* c, const uint32_t* a,
                                     uint32_t b0, uint32_t b1) {
    asm volatile(
        "mma.sync.aligned.m16n8k8.row.col.f32.tf32.tf32.f32 "
        "{%0,%1,%2,%3}, {%4,%5,%6,%7}, {%8,%9}, {%0,%1,%2,%3};"
        : "+f"(c[0]), "+f"(c[1]), "+f"(c[2]), "+f"(c[3])
        : "r"(a[0]), "r"(a[1]), "r"(a[2]), "r"(a[3]), "r"(b0), "r"(b1));
}
__device__ __forceinline__ void ldsm4(uint32_t addr, uint32_t* r) {
    asm volatile("ldmatrix.sync.aligned.m8n8.x4.shared.b16 {%0,%1,%2,%3}, [%4];"
                 : "=r"(r[0]), "=r"(r[1]), "=r"(r[2]), "=r"(r[3]) : "r"(addr));
}
__device__ __forceinline__ void cpa16(uint32_t dst, const void* src) {
    asm volatile("cp.async.cg.shared.global [%0], [%1], 16;" :: "r"(dst), "l"(src));
}
__device__ __forceinline__ void cpa_commit() { asm volatile("cp.async.commit_group;"); }
template <int N>
__device__ __forceinline__ void cpa_wait() {
    asm volatile("cp.async.wait_group %0;" :: "n"(N));
}

// ---------------------------------------------------------------------------
// Pre-pass 1: elementwise tf32 rounding (x -> g_xtf), float4 vectorized.
// ---------------------------------------------------------------------------
__global__ void cvt_tf32_kernel(const float* __restrict__ in,
                                float* __restrict__ out, int n4) {
    int i = blockIdx.x * blockDim.x + threadIdx.x;
    if (i < n4) {
        float4 v = reinterpret_cast<const float4*>(in)[i];
        v.x = __uint_as_float(f2tf(v.x));
        v.y = __uint_as_float(f2tf(v.y));
        v.z = __uint_as_float(f2tf(v.z));
        v.w = __uint_as_float(f2tf(v.w));
        reinterpret_cast<float4*>(out)[i] = v;
    }
}

// ---------------------------------------------------------------------------
// Pre-pass 2: WT[C][R] = tf32(W[R][C])
// ---------------------------------------------------------------------------
__global__ void transpose_cvt_kernel(const float* __restrict__ W,
                                     float* __restrict__ WT, int R, int C) {
    __shared__ float t[32][33];
    int c0 = blockIdx.x * 32, r0 = blockIdx.y * 32;
    int x = threadIdx.x, y = threadIdx.y;   // block (32, 8)
    #pragma unroll
    for (int i = 0; i < 32; i += 8)
        t[y + i][x] = __uint_as_float(f2tf(W[(size_t)(r0 + y + i) * C + c0 + x]));
    __syncthreads();
    #pragma unroll
    for (int i = 0; i < 32; i += 8)
        WT[(size_t)(c0 + y + i) * R + r0 + x] = t[x][y + i];
}

// ---------------------------------------------------------------------------
// GEMM: C[M,N] = A[M,K] * BT[N,K] (+bias). A,BT already tf32 values.
// Block 128x128, BK=32, 256 thr, 8 warps (2m x 4n), warp tile 64x32.
// cp.async double-buffered + ldmatrix. CVTOUT: round outputs to tf32.
// ---------------------------------------------------------------------------
template <bool BIAS, bool CVTOUT>
__global__ __launch_bounds__(256) void gemm_kernel(
    const float* __restrict__ A, const float* __restrict__ BT,
    const float* __restrict__ bias, float* __restrict__ C, int N, int K)
{
    extern __shared__ float sm[];
    const int TSZ = 128 * 36;

    const int tid  = threadIdx.x;
    const int lane = tid & 31;
    const int warp = tid >> 5;
    const int g    = lane >> 2;
    const int cc   = lane & 3;
    const int wr   = warp >> 2;     // 0..1
    const int wc   = warp & 3;      // 0..3
    const int bm   = blockIdx.y * 128;
    const int bn   = blockIdx.x * 128;

    const uint32_t smb  = (uint32_t)__cvta_generic_to_shared(sm);
    const uint32_t bOff = 2u * TSZ * 4;

    const int ldrow = tid >> 3;
    const int ldcol = (tid & 7) * 4;
    const uint32_t aDst = smb + (ldrow * 36 + ldcol) * 4;
    const uint32_t bDst = smb + bOff + (ldrow * 36 + ldcol) * 4;
    const float* aSrc = A  + (size_t)(bm + ldrow) * K + ldcol;
    const float* bSrc = BT + (size_t)(bn + ldrow) * K + ldcol;

    const int rowpat = (lane & 7) + ((lane >> 3) & 1) * 8;
    const int colpat = (lane >> 4) * 4;
    uint32_t aLd[4], bLd[2];
    #pragma unroll
    for (int mt = 0; mt < 4; mt++)
        aLd[mt] = smb + ((wr * 64 + mt * 16 + rowpat) * 36 + colpat) * 4;
    #pragma unroll
    for (int np = 0; np < 2; np++)
        bLd[np] = smb + bOff + ((wc * 32 + np * 16 + rowpat) * 36 + colpat) * 4;

    float acc[4][4][4];
    #pragma unroll
    for (int mt = 0; mt < 4; mt++)
        #pragma unroll
        for (int nt = 0; nt < 4; nt++)
            #pragma unroll
            for (int r = 0; r < 4; r++) acc[mt][nt][r] = 0.f;

    const int NIT = K >> 5;

    #pragma unroll
    for (int i = 0; i < 4; i++) cpa16(aDst + i * 4608, aSrc + (size_t)i * 32 * K);
    #pragma unroll
    for (int i = 0; i < 4; i++) cpa16(bDst + i * 4608, bSrc + (size_t)i * 32 * K);
    cpa_commit();

    for (int it = 0; it < NIT; ++it) {
        const int cur = it & 1;
        if (it + 1 < NIT) {
            const int ko = (it + 1) * 32;
            const uint32_t sa = aDst + (cur ^ 1) * (TSZ * 4);
            const uint32_t sb = bDst + (cur ^ 1) * (TSZ * 4);
            #pragma unroll
            for (int i = 0; i < 4; i++) cpa16(sa + i * 4608, aSrc + (size_t)i * 32 * K + ko);
            #pragma unroll
            for (int i = 0; i < 4; i++) cpa16(sb + i * 4608, bSrc + (size_t)i * 32 * K + ko);
            cpa_commit();
            cpa_wait<1>();
        } else {
            cpa_wait<0>();
        }
        __syncthreads();

        const uint32_t st = cur * (TSZ * 4);
        #pragma unroll
        for (int kk = 0; kk < 4; kk++) {
            uint32_t af[4][4], bq[2][4];
            #pragma unroll
            for (int mt = 0; mt < 4; mt++) ldsm4(aLd[mt] + st + kk * 32, af[mt]);
            ldsm4(bLd[0] + st + kk * 32, bq[0]);
            ldsm4(bLd[1] + st + kk * 32, bq[1]);
            #pragma unroll
            for (int mt = 0; mt < 4; mt++) {
                mma8(acc[mt][0], af[mt], bq[0][0], bq[0][2]);
                mma8(acc[mt][1], af[mt], bq[0][1], bq[0][3]);
                mma8(acc[mt][2], af[mt], bq[1][0], bq[1][2]);
                mma8(acc[mt][3], af[mt], bq[1][1], bq[1][3]);
            }
        }
        __syncthreads();
    }

    #pragma unroll
    for (int mt = 0; mt < 4; mt++) {
        #pragma unroll
        for (int nt = 0; nt < 4; nt++) {
            int row = bm + wr * 64 + mt * 16 + g;
            int col = bn + wc * 32 + nt * 8 + cc * 2;
            float b0 = 0.f, b1 = 0.f;
            if (BIAS) { b0 = bias[col]; b1 = bias[col + 1]; }
            float2 v0, v1;
            if (CVTOUT) {
                v0 = make_float2(__uint_as_float(f2tf(acc[mt][nt][0] + b0)),
                                 __uint_as_float(f2tf(acc[mt][nt][1] + b1)));
                v1 = make_float2(__uint_as_float(f2tf(acc[mt][nt][2] + b0)),
                                 __uint_as_float(f2tf(acc[mt][nt][3] + b1)));
            } else {
                v0 = make_float2(acc[mt][nt][0] + b0, acc[mt][nt][1] + b1);
                v1 = make_float2(acc[mt][nt][2] + b0, acc[mt][nt][3] + b1);
            }
            *reinterpret_cast<float2*>(&C[(size_t)row * N + col])       = v0;
            *reinterpret_cast<float2*>(&C[(size_t)(row + 8) * N + col]) = v1;
        }
    }
}

// ---------------------------------------------------------------------------
// Local attention, one block per (hq, head, b). 4 warps x 16 q-cols.
// qkv already tf32-valued -> fills are pure cp.async copies.
// Q scale (x0.125, exact pow2) applied to fragments in registers.
// K/Q/P smem stride 68 (LDSM-friendly); V stride 72 (conflict-free scalar LDS).
// ---------------------------------------------------------------------------
__global__ __launch_bounds__(128) void attn_kernel(
    const float* __restrict__ qkv, float* __restrict__ attout)
{
    extern __shared__ float sm[];
    float* Qs = sm;                  // 64*68; reused as P buffer
    float* Ks = sm + 64 * 68;        // 64*68
    float* Vs = sm + 2 * 64 * 68;    // 64*72

    const int tid  = threadIdx.x;
    const int lane = tid & 31;
    const int warp = tid >> 5;
    const int g    = lane >> 2;
    const int cc   = lane & 3;
    const int hq   = blockIdx.x;
    const int head = blockIdx.y;
    const int b    = blockIdx.z;
    const int qrow = warp * 16;
    const int k0   = (qrow - 8 < 0) ? 0 : (qrow - 8 > 32 ? 32 : qrow - 8);

    const uint32_t smb = (uint32_t)__cvta_generic_to_shared(sm);
    const int rowpat = (lane & 7) + ((lane >> 3) & 1) * 8;
    const int colpat = (lane >> 4) * 4;
    const uint32_t ksB = smb + (64 * 68) * 4;
    const uint32_t vsB = smb + (2 * 64 * 68) * 4;
    uint32_t kAddr[2];
    #pragma unroll
    for (int np = 0; np < 2; np++)
        kAddr[np] = ksB + ((k0 + np * 16 + rowpat) * 68 + colpat) * 4;
    const uint32_t pAddr = smb + ((qrow + rowpat) * 68 + colpat) * 4;

    // per-thread fill pattern: 8 chunks of 16B each for a 64x64 tile
    const int frow = tid >> 4;          // +8 per iter
    const int fcol = (tid & 15) * 4;

    // ---- Load Q via cp.async (already tf32) ----
    {
        const float* qb = qkv + ((size_t)(b * NTOK + hq * 64)) * QKVC + head * 64;
        #pragma unroll
        for (int i = 0; i < 8; i++)
            cpa16(smb + (((frow + i * 8) * 68 + fcol) * 4),
                  qb + (size_t)(frow + i * 8) * QKVC + fcol);
        cpa_commit();
        cpa_wait<0>();
    }
    __syncthreads();

    uint32_t qa[8][4];
    #pragma unroll
    for (int kk = 0; kk < 8; kk++) {
        ldsm4(pAddr + kk * 32, qa[kk]);
        #pragma unroll
        for (int r = 0; r < 4; r++)
            qa[kk][r] = __float_as_uint(__uint_as_float(qa[kk][r]) * 0.125f);
    }
    __syncthreads();                 // Qs free -> P buffer

    float o[8][4];
    #pragma unroll
    for (int nt = 0; nt < 8; nt++)
        #pragma unroll
        for (int r = 0; r < 4; r++) o[nt][r] = 0.f;
    float mrun[2] = {-1e30f, -1e30f};
    float lrun[2] = {0.f, 0.f};

    const int kh0 = (hq - 3 > 0)  ? hq - 3 : 0;
    const int kh1 = (hq + 3 < 15) ? hq + 3 : 15;

    for (int kh = kh0; kh <= kh1; kh++) {
        const float* kb = qkv + ((size_t)(b * NTOK + kh * 64)) * QKVC + DIMSZ + head * 64;
        const float* vb = kb + DIMSZ;
        #pragma unroll
        for (int i = 0; i < 8; i++) {
            const size_t goff = (size_t)(frow + i * 8) * QKVC + fcol;
            cpa16(ksB + (((frow + i * 8) * 68 + fcol) * 4), kb + goff);
            cpa16(vsB + (((frow + i * 8) * 72 + fcol) * 4), vb + goff);
        }
        cpa_commit();
        cpa_wait<0>();
        __syncthreads();

        // ---- S = Q K^T over this warp's 32-key window ----
        float s[4][4];
        #pragma unroll
        for (int nt = 0; nt < 4; nt++)
            #pragma unroll
            for (int r = 0; r < 4; r++) s[nt][r] = 0.f;

        #pragma unroll
        for (int kk = 0; kk < 8; kk++) {
            #pragma unroll
            for (int np = 0; np < 2; np++) {
                uint32_t kq[4];
                ldsm4(kAddr[np] + kk * 32, kq);
                mma8(s[2 * np    ], qa[kk], kq[0], kq[2]);
                mma8(s[2 * np + 1], qa[kk], kq[1], kq[3]);
            }
        }

        // ---- Mask + online softmax ----
        float mloc[2] = {mrun[0], mrun[1]};
        #pragma unroll
        for (int nt = 0; nt < 4; nt++) {
            #pragma unroll
            for (int r = 0; r < 4; r++) {
                int qw = qrow + g + ((r >> 1) << 3);
                int kw = k0 + nt * 8 + cc * 2 + (r & 1);
                int d  = qw - kw;
                if (d > 5 || d < -5) s[nt][r] = -1e30f;
                mloc[r >> 1] = fmaxf(mloc[r >> 1], s[nt][r]);
            }
        }
        #pragma unroll
        for (int h = 0; h < 2; h++) {
            mloc[h] = fmaxf(mloc[h], __shfl_xor_sync(0xffffffffu, mloc[h], 1));
            mloc[h] = fmaxf(mloc[h], __shfl_xor_sync(0xffffffffu, mloc[h], 2));
        }
        float alpha[2];
        #pragma unroll
        for (int h = 0; h < 2; h++) {
            alpha[h] = __expf(mrun[h] - mloc[h]);
            mrun[h]  = mloc[h];
        }
        float rs[2] = {0.f, 0.f};
        #pragma unroll
        for (int nt = 0; nt < 4; nt++) {
            #pragma unroll
            for (int r = 0; r < 4; r++) {
                float p = __expf(s[nt][r] - mrun[r >> 1]);
                s[nt][r] = p;
                rs[r >> 1] += p;
            }
        }
        #pragma unroll
        for (int h = 0; h < 2; h++) {
            rs[h] += __shfl_xor_sync(0xffffffffu, rs[h], 1);
            rs[h] += __shfl_xor_sync(0xffffffffu, rs[h], 2);
            lrun[h] = lrun[h] * alpha[h] + rs[h];
        }
        #pragma unroll
        for (int nt = 0; nt < 8; nt++)
            #pragma unroll
            for (int r = 0; r < 4; r++) o[nt][r] *= alpha[r >> 1];

        // ---- P (16x32, window-relative cols) -> smem -> A-frags ----
        float* Ps = Qs;
        #pragma unroll
        for (int nt = 0; nt < 4; nt++) {
            float2 p0 = make_float2(__uint_as_float(f2tf(s[nt][0])),
                                    __uint_as_float(f2tf(s[nt][1])));
            float2 p1 = make_float2(__uint_as_float(f2tf(s[nt][2])),
                                    __uint_as_float(f2tf(s[nt][3])));
            *reinterpret_cast<float2*>(&Ps[(qrow + g    ) * 68 + nt * 8 + cc * 2]) = p0;
            *reinterpret_cast<float2*>(&Ps[(qrow + g + 8) * 68 + nt * 8 + cc * 2]) = p1;
        }
        __syncwarp();

        // ---- O += P V  (32-key contraction, conflict-free V) ----
        #pragma unroll
        for (int kk = 0; kk < 4; kk++) {
            uint32_t pa[4];
            ldsm4(pAddr + kk * 32, pa);
            const int krow = k0 + kk * 8;
            #pragma unroll
            for (int nt = 0; nt < 8; nt++) {
                uint32_t vf0 = __float_as_uint(Vs[(krow + cc    ) * 72 + nt * 8 + g]);
                uint32_t vf1 = __float_as_uint(Vs[(krow + cc + 4) * 72 + nt * 8 + g]);
                mma8(o[nt], pa, vf0, vf1);
            }
        }
        __syncthreads();
    }

    float inv[2] = {1.f / lrun[0], 1.f / lrun[1]};
    float* ob = attout + ((size_t)(b * NTOK + hq * 64)) * DIMSZ + head * 64;
    #pragma unroll
    for (int nt = 0; nt < 8; nt++) {
        int col = nt * 8 + cc * 2;
        float2 v0 = make_float2(__uint_as_float(f2tf(o[nt][0] * inv[0])),
                                __uint_as_float(f2tf(o[nt][1] * inv[0])));
        float2 v1 = make_float2(__uint_as_float(f2tf(o[nt][2] * inv[1])),
                                __uint_as_float(f2tf(o[nt][3] * inv[1])));
        *reinterpret_cast<float2*>(&ob[(size_t)(qrow + g    ) * DIMSZ + col]) = v0;
        *reinterpret_cast<float2*>(&ob[(size_t)(qrow + g + 8) * DIMSZ + col]) = v1;
    }
}

// ---------------------------------------------------------------------------
extern "C" void kernel_launch(void* const* d_in, const int* in_sizes, int n_in,
                              void* d_out, int out_size)
{
    (void)in_sizes; (void)n_in; (void)out_size;
    const float* x      = (const float*)d_in[0];
    const float* w_qkv  = (const float*)d_in[1];
    const float* w_proj = (const float*)d_in[2];
    const float* b_proj = (const float*)d_in[3];
    float* out = (float*)d_out;

    float *qkv_ptr, *att_ptr, *xtf_ptr, *wqkvT, *wprojT;
    cudaGetSymbolAddress((void**)&qkv_ptr, g_qkv);
    cudaGetSymbolAddress((void**)&att_ptr, g_att);
    cudaGetSymbolAddress((void**)&xtf_ptr, g_xtf);
    cudaGetSymbolAddress((void**)&wqkvT, g_wqkvT);
    cudaGetSymbolAddress((void**)&wprojT, g_wprojT);

    const int gemm_smem = 4 * 128 * 36 * (int)sizeof(float);             // 73728
    const int attn_smem = (2 * 64 * 68 + 64 * 72) * (int)sizeof(float);  // 53248
    cudaFuncSetAttribute((const void*)gemm_kernel<false, true>,
                         cudaFuncAttributeMaxDynamicSharedMemorySize, gemm_smem);
    cudaFuncSetAttribute((const void*)gemm_kernel<true, false>,
                         cudaFuncAttributeMaxDynamicSharedMemorySize, gemm_smem);
    cudaFuncSetAttribute((const void*)attn_kernel,
                         cudaFuncAttributeMaxDynamicSharedMemorySize, attn_smem);

    // 0) Pre-passes: x -> tf32, weights -> transposed tf32
    const int n4 = MTOT * DIMSZ / 4;
    cvt_tf32_kernel<<<(n4 + 255) / 256, 256>>>(x, xtf_ptr, n4);
    transpose_cvt_kernel<<<dim3(QKVC / 32, DIMSZ / 32), dim3(32, 8)>>>(
        w_qkv, wqkvT, DIMSZ, QKVC);
    transpose_cvt_kernel<<<dim3(DIMSZ / 32, DIMSZ / 32), dim3(32, 8)>>>(
        w_proj, wprojT, DIMSZ, DIMSZ);

    // 1) QKV GEMM (outputs tf32-rounded)
    gemm_kernel<false, true><<<dim3(QKVC / 128, MTOT / 128), 256, gemm_smem>>>(
        xtf_ptr, wqkvT, nullptr, qkv_ptr, QKVC, DIMSZ);

    // 2) Local attention (pure-copy fills; output tf32-rounded)
    attn_kernel<<<dim3(16, 8, BATCH), 128, attn_smem>>>(qkv_ptr, att_ptr);

    // 3) Projection (plain fp32 output + bias)
    gemm_kernel<true, false><<<dim3(DIMSZ / 128, MTOT / 128), 256, gemm_smem>>>(
        att_ptr, wprojT, b_proj, out, DIMSZ, DIMSZ);
}